// round 1
// baseline (speedup 1.0000x reference)
#include <cuda_runtime.h>

#define Bsz 8
#define Nn 2048
#define TMr 16
#define TKc 256
#define SSTR 2052
#define KTSTR 260
#define CAP 1024

// dynamic smem layout (in floats)
#define OFF_U   32832              // union: Kt tile (64x260) / sIdx (16*1024 ints)
#define OFF_Q   49472              // Q tile 16x68
#define OFF_M   50560
#define OFF_L   50576
#define OFF_CNT 50592
#define SMEM_FLOATS 50624          // 202,496 bytes

__device__ float g_Q [Bsz * Nn * 64];
__device__ float g_Kt[Bsz * 64 * Nn];
__device__ float g_V [Bsz * Nn * 64];

// ---------------------------------------------------------------------------
// Kernel 1: QKV projection. 64 rows of x per block; W column cached in regs.
// K is written TRANSPOSED (g_Kt[b][d][n]) so the attention kernel gets
// coalesced, conflict-free K tiles.
// ---------------------------------------------------------------------------
__global__ __launch_bounds__(256) void qkv_kernel(
    const float* __restrict__ x,
    const float* __restrict__ Wq, const float* __restrict__ bq,
    const float* __restrict__ Wk, const float* __restrict__ bk,
    const float* __restrict__ Wv, const float* __restrict__ bv)
{
    __shared__ float sX[64 * 68];
    int tid = threadIdx.x;
    size_t base = (size_t)blockIdx.x * 64;

#pragma unroll
    for (int i = 0; i < 4; i++) {
        int slot = i * 256 + tid;          // 1024 float4 slots
        int row  = slot >> 4;
        int d4   = (slot & 15) << 2;
        float4 v = *(const float4*)(x + (base + row) * 64 + d4);
        *(float4*)(sX + row * 68 + d4) = v;
    }
    __syncthreads();

    int c  = tid & 63;
    int rg = tid >> 6;                     // 0..3 -> 16 rows each
    int b  = (int)(base >> 11);
    int n0 = (int)(base & 2047);

#pragma unroll 1
    for (int m = 0; m < 3; m++) {
        const float* W  = (m == 0) ? Wq : (m == 1) ? Wk : Wv;
        const float* bb = (m == 0) ? bq : (m == 1) ? bk : bv;
        float wcol[64];
#pragma unroll
        for (int d = 0; d < 64; d++) wcol[d] = W[d * 64 + c];
        float bias = bb[c];

#pragma unroll 1
        for (int rr = 0; rr < 16; rr++) {
            int r = rg * 16 + rr;
            const float* xr = sX + r * 68;
            float a0 = 0.f, a1 = 0.f, a2 = 0.f, a3 = 0.f;
#pragma unroll
            for (int d = 0; d < 64; d += 4) {
                float4 xv = *(const float4*)(xr + d);
                a0 += xv.x * wcol[d];
                a1 += xv.y * wcol[d + 1];
                a2 += xv.z * wcol[d + 2];
                a3 += xv.w * wcol[d + 3];
            }
            float acc = ((a0 + a1) + (a2 + a3)) + bias;
            int n = n0 + r;
            if      (m == 0) g_Q [((size_t)b * Nn + n) * 64 + c] = acc;
            else if (m == 1) g_Kt[(size_t)b * (64 * Nn) + (size_t)c * Nn + n] = acc;
            else             g_V [((size_t)b * Nn + n) * 64 + c] = acc;
        }
    }
}

// ---------------------------------------------------------------------------
// Kernel 2: fused attention. One block = (batch b, 16 query rows).
// Full 16x2048 exp-score strip lives in smem -> exact softmax in one K pass.
// mean(probs) == sum(probs)/2048, so mask is e > L/2048. Nonzeros are
// ballot-compacted per row (deterministic order) and P·V is a sparse gather.
// ---------------------------------------------------------------------------
__global__ __launch_bounds__(256) void attn_kernel(float* __restrict__ out)
{
    extern __shared__ float sm[];
    float* sS   = sm;
    float* sU   = sm + OFF_U;
    float* sQ   = sm + OFF_Q;
    float* sM   = sm + OFF_M;
    float* sL   = sm + OFF_L;
    int*   sCnt = (int*)(sm + OFF_CNT);
    int*   sIdx = (int*)sU;

    int tid = threadIdx.x;
    int b   = blockIdx.y;
    int i0  = blockIdx.x * TMr;

    // load Q tile [16][64] -> sQ
    {
        int row = tid >> 4, d4 = (tid & 15) << 2;
        float4 v = *(const float4*)(g_Q + ((size_t)b * Nn + i0 + row) * 64 + d4);
        *(float4*)(sQ + row * 68 + d4) = v;
    }

    int cg = tid & 63;     // column group: 4 cols each
    int rg = tid >> 6;     // row group: 4 rows each

    // ---- scores: S = Q K^T, tile TK=256 over keys ----
    for (int jt = 0; jt < Nn; jt += TKc) {
        __syncthreads();
        const float* ktg = g_Kt + (size_t)b * (64 * Nn) + jt;
#pragma unroll
        for (int i = 0; i < 16; i++) {
            int slot = i * 256 + tid;          // 4096 float4 slots
            int d  = slot >> 6;
            int j4 = (slot & 63) << 2;
            float4 v = *(const float4*)(ktg + (size_t)d * Nn + j4);
            *(float4*)(sU + d * KTSTR + j4) = v;
        }
        __syncthreads();

        float s[4][4];
#pragma unroll
        for (int i = 0; i < 4; i++)
#pragma unroll
            for (int j = 0; j < 4; j++) s[i][j] = 0.f;

#pragma unroll
        for (int d4 = 0; d4 < 64; d4 += 4) {
            float qv[4][4], kv[4][4];
#pragma unroll
            for (int i = 0; i < 4; i++)
                *(float4*)&qv[i][0] = *(const float4*)(sQ + (4 * rg + i) * 68 + d4);
#pragma unroll
            for (int dd = 0; dd < 4; dd++)
                *(float4*)&kv[dd][0] = *(const float4*)(sU + (d4 + dd) * KTSTR + 4 * cg);
#pragma unroll
            for (int i = 0; i < 4; i++)
#pragma unroll
                for (int dd = 0; dd < 4; dd++)
#pragma unroll
                    for (int cc = 0; cc < 4; cc++)
                        s[i][cc] += qv[i][dd] * kv[dd][cc];
        }
#pragma unroll
        for (int i = 0; i < 4; i++)
            *(float4*)(sS + (4 * rg + i) * SSTR + jt + 4 * cg) =
                make_float4(s[i][0], s[i][1], s[i][2], s[i][3]);
    }
    __syncthreads();

    int wid = tid >> 5, lane = tid & 31;

    // ---- pass A: row max ----
#pragma unroll
    for (int rr = 0; rr < 2; rr++) {
        int row = wid * 2 + rr;
        float m = -1e30f;
        for (int j4 = lane * 4; j4 < Nn; j4 += 128) {
            float4 v = *(const float4*)(sS + row * SSTR + j4);
            m = fmaxf(m, fmaxf(fmaxf(v.x, v.y), fmaxf(v.z, v.w)));
        }
#pragma unroll
        for (int o = 16; o > 0; o >>= 1)
            m = fmaxf(m, __shfl_xor_sync(0xffffffffu, m, o));
        if (lane == 0) sM[row] = m;
    }
    __syncthreads();

    // ---- pass B: e = exp(s - max) in place, row sum ----
#pragma unroll
    for (int rr = 0; rr < 2; rr++) {
        int row = wid * 2 + rr;
        float M = sM[row];
        float sum = 0.f;
        for (int j4 = lane * 4; j4 < Nn; j4 += 128) {
            float4 v = *(const float4*)(sS + row * SSTR + j4);
            v.x = __expf(v.x - M);
            v.y = __expf(v.y - M);
            v.z = __expf(v.z - M);
            v.w = __expf(v.w - M);
            sum += (v.x + v.y) + (v.z + v.w);
            *(float4*)(sS + row * SSTR + j4) = v;
        }
#pragma unroll
        for (int o = 16; o > 0; o >>= 1)
            sum += __shfl_xor_sync(0xffffffffu, sum, o);
        if (lane == 0) sL[row] = sum;
    }
    __syncthreads();

    // ---- pass C: mask (e > L/2048), deterministic nonzero compaction ----
#pragma unroll
    for (int rr = 0; rr < 2; rr++) {
        int row = wid * 2 + rr;
        float thr = sL[row] * (1.0f / 2048.0f);
        int cnt = 0;
        for (int cb = 0; cb < Nn; cb += 32) {
            int j = cb + lane;
            float e = sS[row * SSTR + j];
            bool keep = e > thr;
            unsigned msk = __ballot_sync(0xffffffffu, keep);
            if (keep) {
                int pos = cnt + __popc(msk & ((1u << lane) - 1u));
                if (pos < CAP) sIdx[row * CAP + pos] = j;
            } else {
                sS[row * SSTR + j] = 0.f;
            }
            cnt += __popc(msk);
        }
        if (lane == 0) sCnt[row] = cnt;
    }
    __syncthreads();

    // ---- P·V: sparse gather of V rows from L2 ----
    int r  = tid >> 4;
    int tx = (tid & 15) << 2;
    int cnt = sCnt[r];
    float invL = 1.0f / sL[r];
    const float* vb   = g_V + (size_t)b * Nn * 64;
    const float* srow = sS + r * SSTR;
    float4 acc = make_float4(0.f, 0.f, 0.f, 0.f);

    if (cnt <= CAP) {
        const int* lst = sIdx + r * CAP;
        int i = 0;
        for (; i + 4 <= cnt; i += 4) {
            int k0 = lst[i], k1 = lst[i + 1], k2 = lst[i + 2], k3 = lst[i + 3];
            float w0 = srow[k0], w1 = srow[k1], w2 = srow[k2], w3 = srow[k3];
            float4 v0 = *(const float4*)(vb + (size_t)k0 * 64 + tx);
            float4 v1 = *(const float4*)(vb + (size_t)k1 * 64 + tx);
            float4 v2 = *(const float4*)(vb + (size_t)k2 * 64 + tx);
            float4 v3 = *(const float4*)(vb + (size_t)k3 * 64 + tx);
            acc.x += w0 * v0.x; acc.y += w0 * v0.y; acc.z += w0 * v0.z; acc.w += w0 * v0.w;
            acc.x += w1 * v1.x; acc.y += w1 * v1.y; acc.z += w1 * v1.z; acc.w += w1 * v1.w;
            acc.x += w2 * v2.x; acc.y += w2 * v2.y; acc.z += w2 * v2.z; acc.w += w2 * v2.w;
            acc.x += w3 * v3.x; acc.y += w3 * v3.y; acc.z += w3 * v3.z; acc.w += w3 * v3.w;
        }
        for (; i < cnt; i++) {
            int k = lst[i];
            float w = srow[k];
            float4 v = *(const float4*)(vb + (size_t)k * 64 + tx);
            acc.x += w * v.x; acc.y += w * v.y; acc.z += w * v.z; acc.w += w * v.w;
        }
    } else {
        // dense fallback (list overflow) — exact same math
        for (int k = 0; k < Nn; k++) {
            float w = srow[k];
            if (w > 0.f) {
                float4 v = *(const float4*)(vb + (size_t)k * 64 + tx);
                acc.x += w * v.x; acc.y += w * v.y; acc.z += w * v.z; acc.w += w * v.w;
            }
        }
    }

    acc.x *= invL; acc.y *= invL; acc.z *= invL; acc.w *= invL;
    *(float4*)(out + ((size_t)b * Nn + i0 + r) * 64 + tx) = acc;
}

// ---------------------------------------------------------------------------
extern "C" void kernel_launch(void* const* d_in, const int* in_sizes, int n_in,
                              void* d_out, int out_size)
{
    const float* x  = (const float*)d_in[0];
    const float* Wq = (const float*)d_in[1];
    const float* bq = (const float*)d_in[2];
    const float* Wk = (const float*)d_in[3];
    const float* bk = (const float*)d_in[4];
    const float* Wv = (const float*)d_in[5];
    const float* bv = (const float*)d_in[6];
    float* out = (float*)d_out;

    cudaFuncSetAttribute(attn_kernel,
                         cudaFuncAttributeMaxDynamicSharedMemorySize,
                         SMEM_FLOATS * 4);

    qkv_kernel<<<(Bsz * Nn) / 64, 256>>>(x, Wq, bq, Wk, bk, Wv, bv);
    attn_kernel<<<dim3(Nn / TMr, Bsz), 256, SMEM_FLOATS * 4>>>(out);
}

// round 3
// speedup vs baseline: 1.4115x; 1.4115x over previous
#include <cuda_runtime.h>
#include <cuda_bf16.h>
#include <cstdint>

#define Bsz 8
#define Nn 2048
#define SSTR 2052
#define CAP 1024
#define TK 128

// ---------------- fused kernel smem layout (bytes) ----------------
#define OFF_S    0                   // 16 x 2052 fp32 strip = 131,328
#define OFF_K0   131328              // 2 x (KH 128x144 + KL 128x144) = 73,728
#define KBUF_SZ  36864
#define KHALF    18432
#define OFF_QH   205056
#define OFF_QL   207360              // each Q split 16x144 = 2,304
#define OFF_STAT 209664              // sM 64 | sL 64 | sCnt 64
#define SMEM_TOTAL 209856

__device__ float          g_V [Bsz * Nn * 64];
__device__ __nv_bfloat16  g_Qh[Bsz * Nn * 64];
__device__ __nv_bfloat16  g_Ql[Bsz * Nn * 64];
__device__ __nv_bfloat16  g_Kh[Bsz * Nn * 64];
__device__ __nv_bfloat16  g_Kl[Bsz * Nn * 64];

// ================= helpers =================
__device__ __forceinline__ uint32_t smem_u32(const void* p) {
    uint32_t a;
    asm("{ .reg .u64 t; cvta.to.shared.u64 t, %1; cvt.u32.u64 %0, t; }" : "=r"(a) : "l"(p));
    return a;
}
__device__ __forceinline__ void cp16(uint32_t dst, const void* src) {
    asm volatile("cp.async.cg.shared.global [%0], [%1], 16;" :: "r"(dst), "l"(src));
}
#define CP_COMMIT()  asm volatile("cp.async.commit_group;" ::: "memory")
#define CP_WAIT(n)   asm volatile("cp.async.wait_group %0;" :: "n"(n) : "memory")

__device__ __forceinline__ void mma16816(float* d, const uint32_t* a, const uint32_t* b) {
    asm volatile(
        "mma.sync.aligned.m16n8k16.row.col.f32.bf16.bf16.f32 "
        "{%0,%1,%2,%3}, {%4,%5,%6,%7}, {%8,%9}, {%0,%1,%2,%3};"
        : "+f"(d[0]), "+f"(d[1]), "+f"(d[2]), "+f"(d[3])
        : "r"(a[0]), "r"(a[1]), "r"(a[2]), "r"(a[3]), "r"(b[0]), "r"(b[1]));
}

// ---------------------------------------------------------------------------
// Kernel A: QKV projection -> bf16 hi/lo Q,K splits + fp32 V.
// ---------------------------------------------------------------------------
__global__ __launch_bounds__(256) void qkv_kernel(
    const float* __restrict__ x,
    const float* __restrict__ Wq, const float* __restrict__ bq,
    const float* __restrict__ Wk, const float* __restrict__ bk,
    const float* __restrict__ Wv, const float* __restrict__ bv)
{
    __shared__ float sX[64 * 68];
    int tid = threadIdx.x;
    size_t base = (size_t)blockIdx.x * 64;

#pragma unroll
    for (int i = 0; i < 4; i++) {
        int slot = i * 256 + tid;
        int row  = slot >> 4;
        int d4   = (slot & 15) << 2;
        float4 v = *(const float4*)(x + (base + row) * 64 + d4);
        *(float4*)(sX + row * 68 + d4) = v;
    }
    __syncthreads();

    int c  = tid & 63;
    int rg = tid >> 6;

#pragma unroll 1
    for (int m = 0; m < 3; m++) {
        const float* W  = (m == 0) ? Wq : (m == 1) ? Wk : Wv;
        const float* bb = (m == 0) ? bq : (m == 1) ? bk : bv;
        float wcol[64];
#pragma unroll
        for (int d = 0; d < 64; d++) wcol[d] = W[d * 64 + c];
        float bias = bb[c];

#pragma unroll 1
        for (int rr = 0; rr < 16; rr++) {
            int r = rg * 16 + rr;
            const float* xr = sX + r * 68;
            float a0 = 0.f, a1 = 0.f, a2 = 0.f, a3 = 0.f;
#pragma unroll
            for (int d = 0; d < 64; d += 4) {
                float4 xv = *(const float4*)(xr + d);
                a0 += xv.x * wcol[d];
                a1 += xv.y * wcol[d + 1];
                a2 += xv.z * wcol[d + 2];
                a3 += xv.w * wcol[d + 3];
            }
            float acc = ((a0 + a1) + (a2 + a3)) + bias;
            size_t idx = (base + r) * 64 + c;
            if (m == 2) {
                g_V[idx] = acc;
            } else {
                __nv_bfloat16 hi = __float2bfloat16(acc);
                __nv_bfloat16 lo = __float2bfloat16(acc - __bfloat162float(hi));
                if (m == 0) { g_Qh[idx] = hi; g_Ql[idx] = lo; }
                else        { g_Kh[idx] = hi; g_Kl[idx] = lo; }
            }
        }
    }
}

// ---------------------------------------------------------------------------
// Kernel B (fused): scores via bf16 HMMA 3-term split -> smem strip,
// exact softmax, mean-threshold mask (e > L/2048), sparse P.V gather.
// Block = (batch, 16 query rows), 256 threads, ~205 KB smem, K double-buffered.
// ---------------------------------------------------------------------------
__global__ __launch_bounds__(256, 1) void attn_kernel(float* __restrict__ out)
{
    extern __shared__ char smem[];
    float* sS   = (float*)(smem + OFF_S);
    int*   sIdx = (int*)(smem + OFF_K0);          // union with K buffers (used after GEMM)
    float* sM   = (float*)(smem + OFF_STAT);
    float* sL   = (float*)(smem + OFF_STAT + 64);
    int*   sCnt = (int*)(smem + OFF_STAT + 128);

    uint32_t smem_base = smem_u32(smem);
    int tid  = threadIdx.x;
    int wid  = tid >> 5;
    int lane = tid & 31;
    int b    = blockIdx.y;
    int i0   = blockIdx.x * 16;

    // ---- stage chunk 0 of K (cp.async) ----
    {
        uint32_t kb = smem_base + OFF_K0;
        const __nv_bfloat16* srcH = g_Kh + ((size_t)b * Nn) * 64;
        const __nv_bfloat16* srcL = g_Kl + ((size_t)b * Nn) * 64;
#pragma unroll
        for (int i = 0; i < 4; i++) {
            int slot = i * 256 + tid;           // 1024 x 16B per split
            int row  = slot >> 3;
            int c16  = slot & 7;
            cp16(kb +         row * 144 + c16 * 16, srcH + row * 64 + c16 * 8);
            cp16(kb + KHALF + row * 144 + c16 * 16, srcL + row * 64 + c16 * 8);
        }
        CP_COMMIT();
    }

    // ---- stage Q tile [16][64] hi/lo into padded smem ----
    {
        int half = tid >> 7;                    // 0: hi, 1: lo
        int t    = tid & 127;                   // 128 x 16B per split
        int row  = t >> 3;
        int c16  = t & 7;
        const __nv_bfloat16* src = (half ? g_Ql : g_Qh) + ((size_t)b * Nn + i0 + row) * 64 + c16 * 8;
        uint4 v = *(const uint4*)src;
        *(uint4*)(smem + (half ? OFF_QL : OFF_QH) + row * 144 + c16 * 16) = v;
    }
    __syncthreads();

    // ---- extract A fragments (Q) into registers: 4 k-steps x 4 regs, hi+lo ----
    uint32_t aH[16], aL[16];
    {
        int baseA = (lane >> 2) * 144 + (lane & 3) * 4;
#pragma unroll
        for (int ks = 0; ks < 4; ks++) {
            aH[ks * 4 + 0] = *(const uint32_t*)(smem + OFF_QH + baseA + ks * 32);
            aH[ks * 4 + 1] = *(const uint32_t*)(smem + OFF_QH + baseA + 1152 + ks * 32);
            aH[ks * 4 + 2] = *(const uint32_t*)(smem + OFF_QH + baseA + ks * 32 + 16);
            aH[ks * 4 + 3] = *(const uint32_t*)(smem + OFF_QH + baseA + 1152 + ks * 32 + 16);
            aL[ks * 4 + 0] = *(const uint32_t*)(smem + OFF_QL + baseA + ks * 32);
            aL[ks * 4 + 1] = *(const uint32_t*)(smem + OFF_QL + baseA + 1152 + ks * 32);
            aL[ks * 4 + 2] = *(const uint32_t*)(smem + OFF_QL + baseA + ks * 32 + 16);
            aL[ks * 4 + 3] = *(const uint32_t*)(smem + OFF_QL + baseA + 1152 + ks * 32 + 16);
        }
    }

    // ---- main loop: 16 key chunks of 128, double-buffered ----
#pragma unroll 1
    for (int c = 0; c < 16; c++) {
        if (c < 15) {
            uint32_t kb = smem_base + OFF_K0 + ((c + 1) & 1) * KBUF_SZ;
            int j0 = (c + 1) * TK;
            const __nv_bfloat16* srcH = g_Kh + ((size_t)b * Nn + j0) * 64;
            const __nv_bfloat16* srcL = g_Kl + ((size_t)b * Nn + j0) * 64;
#pragma unroll
            for (int i = 0; i < 4; i++) {
                int slot = i * 256 + tid;
                int row  = slot >> 3;
                int c16  = slot & 7;
                cp16(kb +         row * 144 + c16 * 16, srcH + row * 64 + c16 * 8);
                cp16(kb + KHALF + row * 144 + c16 * 16, srcL + row * 64 + c16 * 8);
            }
            CP_COMMIT();
            CP_WAIT(1);
        } else {
            CP_WAIT(0);
        }
        __syncthreads();

        const char* kh = smem + OFF_K0 + (c & 1) * KBUF_SZ;
        const char* kl = kh + KHALF;

#pragma unroll
        for (int g = 0; g < 2; g++) {
            int n0 = wid * 16 + g * 8;                       // key group within chunk
            int baseB = (n0 + (lane >> 2)) * 144 + (lane & 3) * 4;

            uint32_t bh[8], bl[8];
#pragma unroll
            for (int ks = 0; ks < 4; ks++) {
                bh[ks * 2 + 0] = *(const uint32_t*)(kh + baseB + ks * 32);
                bh[ks * 2 + 1] = *(const uint32_t*)(kh + baseB + ks * 32 + 16);
                bl[ks * 2 + 0] = *(const uint32_t*)(kl + baseB + ks * 32);
                bl[ks * 2 + 1] = *(const uint32_t*)(kl + baseB + ks * 32 + 16);
            }

            float d[4] = {0.f, 0.f, 0.f, 0.f};
#pragma unroll
            for (int ks = 0; ks < 4; ks++) mma16816(d, &aH[ks * 4], &bh[ks * 2]);
#pragma unroll
            for (int ks = 0; ks < 4; ks++) mma16816(d, &aH[ks * 4], &bl[ks * 2]);
#pragma unroll
            for (int ks = 0; ks < 4; ks++) mma16816(d, &aL[ks * 4], &bh[ks * 2]);

            int col = c * TK + n0 + (lane & 3) * 2;
            int r0  = lane >> 2;
            *(float2*)(sS + r0 * SSTR + col)       = make_float2(d[0], d[1]);
            *(float2*)(sS + (r0 + 8) * SSTR + col) = make_float2(d[2], d[3]);
        }
        __syncthreads();
    }

    // ---- pass A: row max ----
#pragma unroll
    for (int rr = 0; rr < 2; rr++) {
        int row = wid * 2 + rr;
        float m = -1e30f;
        for (int j4 = lane * 4; j4 < Nn; j4 += 128) {
            float4 v = *(const float4*)(sS + row * SSTR + j4);
            m = fmaxf(m, fmaxf(fmaxf(v.x, v.y), fmaxf(v.z, v.w)));
        }
#pragma unroll
        for (int o = 16; o > 0; o >>= 1)
            m = fmaxf(m, __shfl_xor_sync(0xffffffffu, m, o));
        if (lane == 0) sM[row] = m;
    }
    __syncthreads();

    // ---- pass B: e = exp(s - max), row sum ----
#pragma unroll
    for (int rr = 0; rr < 2; rr++) {
        int row = wid * 2 + rr;
        float M = sM[row];
        float sum = 0.f;
        for (int j4 = lane * 4; j4 < Nn; j4 += 128) {
            float4 v = *(const float4*)(sS + row * SSTR + j4);
            v.x = __expf(v.x - M);
            v.y = __expf(v.y - M);
            v.z = __expf(v.z - M);
            v.w = __expf(v.w - M);
            sum += (v.x + v.y) + (v.z + v.w);
            *(float4*)(sS + row * SSTR + j4) = v;
        }
#pragma unroll
        for (int o = 16; o > 0; o >>= 1)
            sum += __shfl_xor_sync(0xffffffffu, sum, o);
        if (lane == 0) sL[row] = sum;
    }
    __syncthreads();

    // ---- pass C: mask (e > L/2048), deterministic ballot compaction ----
#pragma unroll
    for (int rr = 0; rr < 2; rr++) {
        int row = wid * 2 + rr;
        float thr = sL[row] * (1.0f / 2048.0f);
        int cnt = 0;
        for (int cb = 0; cb < Nn; cb += 32) {
            int j = cb + lane;
            float e = sS[row * SSTR + j];
            bool keep = e > thr;
            unsigned msk = __ballot_sync(0xffffffffu, keep);
            if (keep) {
                int pos = cnt + __popc(msk & ((1u << lane) - 1u));
                if (pos < CAP) sIdx[row * CAP + pos] = j;
            } else {
                sS[row * SSTR + j] = 0.f;
            }
            cnt += __popc(msk);
        }
        if (lane == 0) sCnt[row] = cnt;
    }
    __syncthreads();

    // ---- P.V: sparse gather of V rows ----
    int r  = tid >> 4;
    int tx = (tid & 15) << 2;
    int cnt = sCnt[r];
    float invL = 1.0f / sL[r];
    const float* vb   = g_V + (size_t)b * Nn * 64;
    const float* srow = sS + r * SSTR;
    float4 acc = make_float4(0.f, 0.f, 0.f, 0.f);

    if (cnt <= CAP) {
        const int* lst = sIdx + r * CAP;
        int i = 0;
        for (; i + 4 <= cnt; i += 4) {
            int k0 = lst[i], k1 = lst[i + 1], k2 = lst[i + 2], k3 = lst[i + 3];
            float w0 = srow[k0], w1 = srow[k1], w2 = srow[k2], w3 = srow[k3];
            float4 v0 = *(const float4*)(vb + (size_t)k0 * 64 + tx);
            float4 v1 = *(const float4*)(vb + (size_t)k1 * 64 + tx);
            float4 v2 = *(const float4*)(vb + (size_t)k2 * 64 + tx);
            float4 v3 = *(const float4*)(vb + (size_t)k3 * 64 + tx);
            acc.x += w0 * v0.x; acc.y += w0 * v0.y; acc.z += w0 * v0.z; acc.w += w0 * v0.w;
            acc.x += w1 * v1.x; acc.y += w1 * v1.y; acc.z += w1 * v1.z; acc.w += w1 * v1.w;
            acc.x += w2 * v2.x; acc.y += w2 * v2.y; acc.z += w2 * v2.z; acc.w += w2 * v2.w;
            acc.x += w3 * v3.x; acc.y += w3 * v3.y; acc.z += w3 * v3.z; acc.w += w3 * v3.w;
        }
        for (; i < cnt; i++) {
            int k = lst[i];
            float w = srow[k];
            float4 v = *(const float4*)(vb + (size_t)k * 64 + tx);
            acc.x += w * v.x; acc.y += w * v.y; acc.z += w * v.z; acc.w += w * v.w;
        }
    } else {
        for (int k = 0; k < Nn; k++) {
            float w = srow[k];
            if (w > 0.f) {
                float4 v = *(const float4*)(vb + (size_t)k * 64 + tx);
                acc.x += w * v.x; acc.y += w * v.y; acc.z += w * v.z; acc.w += w * v.w;
            }
        }
    }

    acc.x *= invL; acc.y *= invL; acc.z *= invL; acc.w *= invL;
    *(float4*)(out + ((size_t)b * Nn + i0 + r) * 64 + tx) = acc;
}

// ---------------------------------------------------------------------------
extern "C" void kernel_launch(void* const* d_in, const int* in_sizes, int n_in,
                              void* d_out, int out_size)
{
    const float* x  = (const float*)d_in[0];
    const float* Wq = (const float*)d_in[1];
    const float* bq = (const float*)d_in[2];
    const float* Wk = (const float*)d_in[3];
    const float* bk = (const float*)d_in[4];
    const float* Wv = (const float*)d_in[5];
    const float* bv = (const float*)d_in[6];
    float* out = (float*)d_out;

    cudaFuncSetAttribute(attn_kernel,
                         cudaFuncAttributeMaxDynamicSharedMemorySize, SMEM_TOTAL);

    qkv_kernel<<<(Bsz * Nn) / 64, 256>>>(x, Wq, bq, Wk, bk, Wv, bv);
    attn_kernel<<<dim3(Nn / 16, Bsz), 256, SMEM_TOTAL>>>(out);
}

// round 4
// speedup vs baseline: 1.7212x; 1.2194x over previous
#include <cuda_runtime.h>
#include <cuda_bf16.h>
#include <cstdint>

#define Bsz 8
#define Nn 2048
#define SSTR 2052
#define CAP 1024
#define TK 128

// ---------------- fused kernel smem layout (bytes) ----------------
#define OFF_S    0                   // 16 x 2052 fp32 strip = 131,328
#define OFF_K0   131328              // 2 x (KH 128x144 + KL 128x144) = 73,728
#define KBUF_SZ  36864
#define KHALF    18432
#define OFF_QH   205056
#define OFF_QL   207360              // each Q split 16x144 = 2,304
#define OFF_STAT 209664              // sM 64 | sL 64 | sCnt 64 | sMp 1024
#define SMEM_TOTAL 210880

__device__ float          g_V [Bsz * Nn * 64];
__device__ __nv_bfloat16  g_Qh[Bsz * Nn * 64];
__device__ __nv_bfloat16  g_Ql[Bsz * Nn * 64];
__device__ __nv_bfloat16  g_Kh[Bsz * Nn * 64];
__device__ __nv_bfloat16  g_Kl[Bsz * Nn * 64];

// ================= helpers =================
__device__ __forceinline__ uint32_t smem_u32(const void* p) {
    uint32_t a;
    asm("{ .reg .u64 t; cvta.to.shared.u64 t, %1; cvt.u32.u64 %0, t; }" : "=r"(a) : "l"(p));
    return a;
}
__device__ __forceinline__ void cp16(uint32_t dst, const void* src) {
    asm volatile("cp.async.cg.shared.global [%0], [%1], 16;" :: "r"(dst), "l"(src));
}
#define CP_COMMIT()  asm volatile("cp.async.commit_group;" ::: "memory")
#define CP_WAIT(n)   asm volatile("cp.async.wait_group %0;" :: "n"(n) : "memory")

#define LDSM_X4(r0, r1, r2, r3, addr)                                          \
    asm volatile("ldmatrix.sync.aligned.m8n8.x4.shared.b16 {%0,%1,%2,%3}, [%4];" \
        : "=r"(r0), "=r"(r1), "=r"(r2), "=r"(r3) : "r"(addr))

__device__ __forceinline__ void mma16816(float* d, const uint32_t* a, const uint32_t* b) {
    asm volatile(
        "mma.sync.aligned.m16n8k16.row.col.f32.bf16.bf16.f32 "
        "{%0,%1,%2,%3}, {%4,%5,%6,%7}, {%8,%9}, {%0,%1,%2,%3};"
        : "+f"(d[0]), "+f"(d[1]), "+f"(d[2]), "+f"(d[3])
        : "r"(a[0]), "r"(a[1]), "r"(a[2]), "r"(a[3]), "r"(b[0]), "r"(b[1]));
}

// ---------------------------------------------------------------------------
// Kernel A: QKV projection -> bf16 hi/lo Q,K splits + fp32 V.
// ---------------------------------------------------------------------------
__global__ __launch_bounds__(256) void qkv_kernel(
    const float* __restrict__ x,
    const float* __restrict__ Wq, const float* __restrict__ bq,
    const float* __restrict__ Wk, const float* __restrict__ bk,
    const float* __restrict__ Wv, const float* __restrict__ bv)
{
    __shared__ float sX[64 * 68];
    int tid = threadIdx.x;
    size_t base = (size_t)blockIdx.x * 64;

#pragma unroll
    for (int i = 0; i < 4; i++) {
        int slot = i * 256 + tid;
        int row  = slot >> 4;
        int d4   = (slot & 15) << 2;
        float4 v = *(const float4*)(x + (base + row) * 64 + d4);
        *(float4*)(sX + row * 68 + d4) = v;
    }
    __syncthreads();

    int c  = tid & 63;
    int rg = tid >> 6;

#pragma unroll 1
    for (int m = 0; m < 3; m++) {
        const float* W  = (m == 0) ? Wq : (m == 1) ? Wk : Wv;
        const float* bb = (m == 0) ? bq : (m == 1) ? bk : bv;
        float wcol[64];
#pragma unroll
        for (int d = 0; d < 64; d++) wcol[d] = W[d * 64 + c];
        float bias = bb[c];

#pragma unroll 1
        for (int rr = 0; rr < 16; rr++) {
            int r = rg * 16 + rr;
            const float* xr = sX + r * 68;
            float a0 = 0.f, a1 = 0.f, a2 = 0.f, a3 = 0.f;
#pragma unroll
            for (int d = 0; d < 64; d += 4) {
                float4 xv = *(const float4*)(xr + d);
                a0 += xv.x * wcol[d];
                a1 += xv.y * wcol[d + 1];
                a2 += xv.z * wcol[d + 2];
                a3 += xv.w * wcol[d + 3];
            }
            float acc = ((a0 + a1) + (a2 + a3)) + bias;
            size_t idx = (base + r) * 64 + c;
            if (m == 2) {
                g_V[idx] = acc;
            } else {
                __nv_bfloat16 hi = __float2bfloat16(acc);
                __nv_bfloat16 lo = __float2bfloat16(acc - __bfloat162float(hi));
                if (m == 0) { g_Qh[idx] = hi; g_Ql[idx] = lo; }
                else        { g_Kh[idx] = hi; g_Kl[idx] = lo; }
            }
        }
    }
}

// ---------------------------------------------------------------------------
// Kernel B (fused): HMMA scores (bf16 hi/lo 3-term) -> smem strip, fused
// row-max, exact softmax, mean-threshold mask, sparse P.V.
// Block = (batch, 16 query rows), 512 threads (16 warps), ~206 KB smem.
// ---------------------------------------------------------------------------
__global__ __launch_bounds__(512, 1) void attn_kernel(float* __restrict__ out)
{
    extern __shared__ char smem[];
    float* sS   = (float*)(smem + OFF_S);
    int*   sIdx = (int*)(smem + OFF_K0);          // union with K buffers
    float* sM   = (float*)(smem + OFF_STAT);
    float* sL   = (float*)(smem + OFF_STAT + 64);
    int*   sCnt = (int*)(smem + OFF_STAT + 128);
    float* sMp  = (float*)(smem + OFF_STAT + 192); // 16 rows x 16 warps

    uint32_t smem_base = smem_u32(smem);
    int tid  = threadIdx.x;
    int wid  = tid >> 5;
    int lane = tid & 31;
    int b    = blockIdx.y;
    int i0   = blockIdx.x * 16;

    // ---- stage chunk 0 of K ----
    {
        uint32_t kb = smem_base + OFF_K0;
        const __nv_bfloat16* srcH = g_Kh + ((size_t)b * Nn) * 64;
        const __nv_bfloat16* srcL = g_Kl + ((size_t)b * Nn) * 64;
#pragma unroll
        for (int i = 0; i < 2; i++) {
            int slot = i * 512 + tid;           // 1024 slots per split
            int row  = slot >> 3;
            int c16  = slot & 7;
            cp16(kb +         row * 144 + c16 * 16, srcH + row * 64 + c16 * 8);
            cp16(kb + KHALF + row * 144 + c16 * 16, srcL + row * 64 + c16 * 8);
        }
        CP_COMMIT();
    }

    // ---- stage Q tile [16][64] hi/lo ----
    if (tid < 256) {
        int half = tid >> 7;
        int t    = tid & 127;
        int row  = t >> 3;
        int c16  = t & 7;
        const __nv_bfloat16* src = (half ? g_Ql : g_Qh) + ((size_t)b * Nn + i0 + row) * 64 + c16 * 8;
        uint4 v = *(const uint4*)src;
        *(uint4*)(smem + (half ? OFF_QL : OFF_QH) + row * 144 + c16 * 16) = v;
    }
    __syncthreads();

    // ---- A fragments via ldmatrix: 4 k-steps x 4 regs, hi + lo ----
    uint32_t aH[16], aL[16];
    {
        uint32_t baseA = (lane & 15) * 144 + (lane >> 4) * 16;
#pragma unroll
        for (int ks = 0; ks < 4; ks++) {
            LDSM_X4(aH[ks * 4], aH[ks * 4 + 1], aH[ks * 4 + 2], aH[ks * 4 + 3],
                    smem_base + OFF_QH + baseA + ks * 32);
            LDSM_X4(aL[ks * 4], aL[ks * 4 + 1], aL[ks * 4 + 2], aL[ks * 4 + 3],
                    smem_base + OFF_QL + baseA + ks * 32);
        }
    }

    int n0 = wid * 8;                        // this warp's key group within chunk
    int r0 = lane >> 2;
    float mx0 = -1e30f, mx1 = -1e30f;

    // ---- main loop: 16 key chunks of 128, double-buffered ----
#pragma unroll 1
    for (int c = 0; c < 16; c++) {
        if (c < 15) {
            uint32_t kb = smem_base + OFF_K0 + ((c + 1) & 1) * KBUF_SZ;
            int j0 = (c + 1) * TK;
            const __nv_bfloat16* srcH = g_Kh + ((size_t)b * Nn + j0) * 64;
            const __nv_bfloat16* srcL = g_Kl + ((size_t)b * Nn + j0) * 64;
#pragma unroll
            for (int i = 0; i < 2; i++) {
                int slot = i * 512 + tid;
                int row  = slot >> 3;
                int c16  = slot & 7;
                cp16(kb +         row * 144 + c16 * 16, srcH + row * 64 + c16 * 8);
                cp16(kb + KHALF + row * 144 + c16 * 16, srcL + row * 64 + c16 * 8);
            }
            CP_COMMIT();
            CP_WAIT(1);
        } else {
            CP_WAIT(0);
        }
        __syncthreads();

        uint32_t kh = smem_base + OFF_K0 + (c & 1) * KBUF_SZ
                    + (uint32_t)(n0 + (lane & 7)) * 144 + (uint32_t)(lane >> 3) * 16;
        uint32_t kl = kh + KHALF;

        uint32_t bh[8], bl[8];
        LDSM_X4(bh[0], bh[1], bh[2], bh[3], kh);
        LDSM_X4(bh[4], bh[5], bh[6], bh[7], kh + 64);
        LDSM_X4(bl[0], bl[1], bl[2], bl[3], kl);
        LDSM_X4(bl[4], bl[5], bl[6], bl[7], kl + 64);

        float d[4] = {0.f, 0.f, 0.f, 0.f};
#pragma unroll
        for (int ks = 0; ks < 4; ks++) mma16816(d, &aH[ks * 4], &bh[ks * 2]);
#pragma unroll
        for (int ks = 0; ks < 4; ks++) mma16816(d, &aH[ks * 4], &bl[ks * 2]);
#pragma unroll
        for (int ks = 0; ks < 4; ks++) mma16816(d, &aL[ks * 4], &bh[ks * 2]);

        mx0 = fmaxf(mx0, fmaxf(d[0], d[1]));
        mx1 = fmaxf(mx1, fmaxf(d[2], d[3]));

        int col = c * TK + n0 + (lane & 3) * 2;
        *(float2*)(sS + r0 * SSTR + col)       = make_float2(d[0], d[1]);
        *(float2*)(sS + (r0 + 8) * SSTR + col) = make_float2(d[2], d[3]);
        __syncthreads();
    }

    // ---- fused row-max: quad shuffle, per-warp partials, tree ----
    mx0 = fmaxf(mx0, __shfl_xor_sync(0xffffffffu, mx0, 1));
    mx0 = fmaxf(mx0, __shfl_xor_sync(0xffffffffu, mx0, 2));
    mx1 = fmaxf(mx1, __shfl_xor_sync(0xffffffffu, mx1, 1));
    mx1 = fmaxf(mx1, __shfl_xor_sync(0xffffffffu, mx1, 2));
    if ((lane & 3) == 0) {
        sMp[r0 * 16 + wid]       = mx0;
        sMp[(r0 + 8) * 16 + wid] = mx1;
    }
    __syncthreads();
    if (tid < 16) {
        float m = -1e30f;
#pragma unroll
        for (int w = 0; w < 16; w++) m = fmaxf(m, sMp[tid * 16 + w]);
        sM[tid] = m;
    }
    __syncthreads();

    // ---- pass B: e = exp(s - max), row sum (one row per warp) ----
    {
        int row = wid;
        float M = sM[row];
        float sum = 0.f;
#pragma unroll 4
        for (int j4 = lane * 4; j4 < Nn; j4 += 128) {
            float4 v = *(const float4*)(sS + row * SSTR + j4);
            v.x = __expf(v.x - M);
            v.y = __expf(v.y - M);
            v.z = __expf(v.z - M);
            v.w = __expf(v.w - M);
            sum += (v.x + v.y) + (v.z + v.w);
            *(float4*)(sS + row * SSTR + j4) = v;
        }
#pragma unroll
        for (int o = 16; o > 0; o >>= 1)
            sum += __shfl_xor_sync(0xffffffffu, sum, o);
        if (lane == 0) sL[row] = sum;
    }
    __syncthreads();

    // ---- pass C: mask (e > L/2048), ballot compaction, no zero-writeback ----
    {
        int row = wid;
        float thr = sL[row] * (1.0f / 2048.0f);
        unsigned lt = (1u << lane) - 1u;
        int cnt = 0;
        int* lst = sIdx + row * CAP;
#pragma unroll 1
        for (int cb = 0; cb < Nn; cb += 128) {
            int j = cb + lane * 4;
            float4 v = *(const float4*)(sS + row * SSTR + j);
            unsigned m0 = __ballot_sync(0xffffffffu, v.x > thr);
            unsigned m1 = __ballot_sync(0xffffffffu, v.y > thr);
            unsigned m2 = __ballot_sync(0xffffffffu, v.z > thr);
            unsigned m3 = __ballot_sync(0xffffffffu, v.w > thr);
            if (v.x > thr) { int p = cnt + __popc(m0 & lt); if (p < CAP) lst[p] = j; }
            cnt += __popc(m0);
            if (v.y > thr) { int p = cnt + __popc(m1 & lt); if (p < CAP) lst[p] = j + 1; }
            cnt += __popc(m1);
            if (v.z > thr) { int p = cnt + __popc(m2 & lt); if (p < CAP) lst[p] = j + 2; }
            cnt += __popc(m2);
            if (v.w > thr) { int p = cnt + __popc(m3 & lt); if (p < CAP) lst[p] = j + 3; }
            cnt += __popc(m3);
        }
        if (lane == 0) sCnt[row] = cnt;
    }
    __syncthreads();

    // ---- P.V: sparse gather of V rows (32 lanes per row, float2) ----
    {
        int r  = tid >> 5;
        int tx = lane * 2;
        int cnt = sCnt[r];
        float Lr = sL[r];
        float invL = 1.0f / Lr;
        float thr = Lr * (1.0f / 2048.0f);
        const float* vb   = g_V + (size_t)b * Nn * 64;
        const float* srow = sS + r * SSTR;
        float2 acc = make_float2(0.f, 0.f);

        if (cnt <= CAP) {
            const int* lst = sIdx + r * CAP;
            int i = 0;
            for (; i + 4 <= cnt; i += 4) {
                int k0 = lst[i], k1 = lst[i + 1], k2 = lst[i + 2], k3 = lst[i + 3];
                float w0 = srow[k0], w1 = srow[k1], w2 = srow[k2], w3 = srow[k3];
                float2 v0 = *(const float2*)(vb + (size_t)k0 * 64 + tx);
                float2 v1 = *(const float2*)(vb + (size_t)k1 * 64 + tx);
                float2 v2 = *(const float2*)(vb + (size_t)k2 * 64 + tx);
                float2 v3 = *(const float2*)(vb + (size_t)k3 * 64 + tx);
                acc.x += w0 * v0.x; acc.y += w0 * v0.y;
                acc.x += w1 * v1.x; acc.y += w1 * v1.y;
                acc.x += w2 * v2.x; acc.y += w2 * v2.y;
                acc.x += w3 * v3.x; acc.y += w3 * v3.y;
            }
            for (; i < cnt; i++) {
                int k = lst[i];
                float w = srow[k];
                float2 v = *(const float2*)(vb + (size_t)k * 64 + tx);
                acc.x += w * v.x; acc.y += w * v.y;
            }
        } else {
            for (int k = 0; k < Nn; k++) {
                float w = srow[k];
                if (w > thr) {
                    float2 v = *(const float2*)(vb + (size_t)k * 64 + tx);
                    acc.x += w * v.x; acc.y += w * v.y;
                }
            }
        }

        acc.x *= invL; acc.y *= invL;
        *(float2*)(out + ((size_t)b * Nn + i0 + r) * 64 + tx) = acc;
    }
}

// ---------------------------------------------------------------------------
extern "C" void kernel_launch(void* const* d_in, const int* in_sizes, int n_in,
                              void* d_out, int out_size)
{
    const float* x  = (const float*)d_in[0];
    const float* Wq = (const float*)d_in[1];
    const float* bq = (const float*)d_in[2];
    const float* Wk = (const float*)d_in[3];
    const float* bk = (const float*)d_in[4];
    const float* Wv = (const float*)d_in[5];
    const float* bv = (const float*)d_in[6];
    float* out = (float*)d_out;

    cudaFuncSetAttribute(attn_kernel,
                         cudaFuncAttributeMaxDynamicSharedMemorySize, SMEM_TOTAL);

    qkv_kernel<<<(Bsz * Nn) / 64, 256>>>(x, Wq, bq, Wk, bk, Wv, bv);
    attn_kernel<<<dim3(Nn / 16, Bsz), 512, SMEM_TOTAL>>>(out);
}